// round 1
// baseline (speedup 1.0000x reference)
#include <cuda_runtime.h>

#define BATCH 16
#define ECH 32
#define NCLS 3
#define HW 262144           // 512*512
#define HW2 131072
#define TILE_PX 512
#define NTILES 512          // HW / TILE_PX
#define GX 37
#define ROWS 514            // smem row stride in floats (even -> aligned STS.64, 2e mod 32 pattern)

// shared memory layout (floats)
#define OFF_VALS 0
#define OFF_META (ECH*ROWS)            // 16448
#define OFF_RED  (OFF_META + TILE_PX)  // 16960
#define OFF_SCR  (OFF_RED + 8*4*32)    // 17984
#define SM_FLOATS (OFF_SCR + 32)       // 18016
#define SMEM_BYTES (SM_FLOATS*4)       // 72064

// global accumulators (scratch via __device__ globals; no allocation)
__device__ float g_acc[BATCH][4][ECH]; // [0]=sum_emb_l1 [1]=sum_hat_l1 [2]=sum_emb_l2 [3]=sum_hat_l2
__device__ float g_cnt[BATCH][2];
__device__ float g_ce;

__global__ void zero_kernel() {
    int i = blockIdx.x * blockDim.x + threadIdx.x;
    if (i < BATCH*4*ECH) (&g_acc[0][0][0])[i] = 0.f;
    if (i < BATCH*2)     (&g_cnt[0][0])[i]   = 0.f;
    if (i == 0)          g_ce = 0.f;
}

__global__ __launch_bounds__(256, 2)
void main_kernel(const float* __restrict__ emb,
                 const float* __restrict__ pred,
                 const int*  __restrict__ lab) {
    extern __shared__ float sm[];
    float* vals  = sm + OFF_VALS;   // [ECH][ROWS]
    float* metaT = sm + OFF_META;   // [TILE_PX] encoded: +rn->label1, -rn->label2, 0->label0
    float* red   = sm + OFF_RED;    // [8][4][32]
    float* scr   = sm + OFF_SCR;

    const int b    = blockIdx.y;
    const int tid  = threadIdx.x;
    const int wid  = tid >> 5;
    const int lane = tid & 31;

    const float2* emb2 = (const float2*)emb + (size_t)b * ECH  * HW2;
    const float2* pr2  = (const float2*)pred + (size_t)b * NCLS * HW2;
    const int2*   lb2  = (const int2*)lab + (size_t)b * HW2;

    // per-lane channel accumulators (lane == channel in phase B)
    float a1 = 0.f, h1 = 0.f, a2 = 0.f, h2 = 0.f;
    float ce = 0.f;
    int   c1 = 0, c2 = 0;

    for (int tile = blockIdx.x; tile < NTILES; tile += GX) {
        const int qp = tile * (TILE_PX / 2) + tid;   // float2 (pixel-pair) index

        // ---------- phase A: coalesced load, per-pixel norm, CE, transpose to smem ----------
        float sx = 0.f, sy = 0.f;
        #pragma unroll 8
        for (int e = 0; e < ECH; e++) {
            float2 v = emb2[e * HW2 + qp];
            sx = fmaf(v.x, v.x, sx);
            sy = fmaf(v.y, v.y, sy);
            *(float2*)&vals[e * ROWS + 2 * tid] = v;
        }
        int2 lp = lb2[qp];
        float rx = 1.f / fmaxf(sqrtf(sx), 1e-8f);
        float ry = 1.f / fmaxf(sqrtf(sy), 1e-8f);
        metaT[2 * tid]     = (lp.x == 1) ? rx : ((lp.x == 2) ? -rx : 0.f);
        metaT[2 * tid + 1] = (lp.y == 1) ? ry : ((lp.y == 2) ? -ry : 0.f);
        c1 += (lp.x == 1) + (lp.y == 1);
        c2 += (lp.x == 2) + (lp.y == 2);

        float2 q0 = pr2[qp], q1 = pr2[HW2 + qp], q2 = pr2[2 * HW2 + qp];
        {
            float m   = fmaxf(q0.x, fmaxf(q1.x, q2.x));
            float lse = m + __logf(__expf(q0.x - m) + __expf(q1.x - m) + __expf(q2.x - m));
            ce += lse - ((lp.x == 0) ? q0.x : ((lp.x == 1) ? q1.x : q2.x));
            m   = fmaxf(q0.y, fmaxf(q1.y, q2.y));
            lse = m + __logf(__expf(q0.y - m) + __expf(q1.y - m) + __expf(q2.y - m));
            ce += lse - ((lp.y == 0) ? q0.y : ((lp.y == 1) ? q1.y : q2.y));
        }
        __syncthreads();

        // ---------- phase B: warp = 32 channels, each warp accumulates 64 pixels ----------
        const float* vrow = vals  + lane * ROWS + wid * 64;
        const float* mrow = metaT + wid * 64;
        #pragma unroll 8
        for (int i = 0; i < 32; i++) {
            float2 v = *(const float2*)(vrow + 2 * i);
            float2 t = *(const float2*)(mrow + 2 * i);   // broadcast within warp
            float vh0 = v.x * fabsf(t.x);
            float vh1 = v.y * fabsf(t.y);
            if      (t.x > 0.f) { a1 += v.x; h1 += vh0; }
            else if (t.x < 0.f) { a2 += v.x; h2 += vh0; }
            if      (t.y > 0.f) { a1 += v.y; h1 += vh1; }
            else if (t.y < 0.f) { a2 += v.y; h2 += vh1; }
        }
        __syncthreads();
    }

    // ---------- block reduction + global atomics ----------
    red[(wid * 4 + 0) * 32 + lane] = a1;
    red[(wid * 4 + 1) * 32 + lane] = h1;
    red[(wid * 4 + 2) * 32 + lane] = a2;
    red[(wid * 4 + 3) * 32 + lane] = h2;
    #pragma unroll
    for (int o = 16; o; o >>= 1) {
        ce += __shfl_xor_sync(0xffffffffu, ce, o);
        c1 += __shfl_xor_sync(0xffffffffu, c1, o);
        c2 += __shfl_xor_sync(0xffffffffu, c2, o);
    }
    if (lane == 0) { scr[wid] = ce; scr[8 + wid] = (float)c1; scr[16 + wid] = (float)c2; }
    __syncthreads();

    if (wid < 4) {
        float s = 0.f;
        #pragma unroll
        for (int w = 0; w < 8; w++) s += red[(w * 4 + wid) * 32 + lane];
        atomicAdd(&g_acc[b][wid][lane], s);
    }
    if (tid == 0) {
        float tce = 0.f, t1 = 0.f, t2 = 0.f;
        for (int w = 0; w < 8; w++) { tce += scr[w]; t1 += scr[8 + w]; t2 += scr[16 + w]; }
        atomicAdd(&g_ce, tce);
        atomicAdd(&g_cnt[b][0], t1);
        atomicAdd(&g_cnt[b][1], t2);
    }
}

__global__ void finalize_kernel(const int* __restrict__ nb, float* __restrict__ out) {
    __shared__ float part[BATCH];
    const int wid  = threadIdx.x >> 5;
    const int lane = threadIdx.x & 31;
    const int b    = wid;   // one warp per image, lane = channel

    float s1 = g_acc[b][0][lane], hh1 = g_acc[b][1][lane];
    float s2 = g_acc[b][2][lane], hh2 = g_acc[b][3][lane];
    float c1 = g_cnt[b][0], c2 = g_cnt[b][1];
    float m1 = s1 / c1, m2 = s2 / c2;

    float A  = m1 * m1;     // ||mean1||^2
    float Bv = m2 * m2;     // ||mean2||^2
    float C  = m1 * m2;     // mean1 . mean2
    float D1 = m1 * hh1;    // mean1 . hat_sum1
    float D2 = m2 * hh2;    // mean2 . hat_sum2
    #pragma unroll
    for (int o = 16; o; o >>= 1) {
        A  += __shfl_xor_sync(0xffffffffu, A,  o);
        Bv += __shfl_xor_sync(0xffffffffu, Bv, o);
        C  += __shfl_xor_sync(0xffffffffu, C,  o);
        D1 += __shfl_xor_sync(0xffffffffu, D1, o);
        D2 += __shfl_xor_sync(0xffffffffu, D2, o);
    }

    if (lane == 0) {
        float n1 = fmaxf(sqrtf(A),  1e-12f);
        float n2 = fmaxf(sqrtf(Bv), 1e-12f);
        float intra = ((1.f - D1 / (n1 * c1)) + (1.f - D2 / (n2 * c2))) / (float)(NCLS - 1);
        float S11 = A  / (n1 * n1);
        float S22 = Bv / (n2 * n2);
        float S12 = C  / (n1 * n2);
        bool mk[NCLS][NCLS] = {};
        for (int r = 1; r < NCLS; r++) {
            for (int j = 0; j < 3; j++) {
                int n = nb[(b * NCLS + r) * 3 + j];
                if (n == 0) break;      // cumprod break semantics
                mk[r][n] = true;        // scatter-max: duplicates count once
            }
        }
        float ssum = 0.f, msum = 0.f;
        for (int r = 1; r < NCLS; r++)
            for (int c = 0; c < NCLS; c++)
                if (mk[r][c]) {
                    msum += 1.f;
                    float Sv = 0.f;
                    if (r == 1) Sv = (c == 1) ? S11 : ((c == 2) ? S12 : 0.f);
                    else        Sv = (c == 1) ? S12 : ((c == 2) ? S22 : 0.f);
                    ssum += Sv;
                }
        part[b] = intra + ssum / msum;
    }
    __syncthreads();
    if (threadIdx.x == 0) {
        float tot = g_ce * (1.0f / (float)HW);
        #pragma unroll
        for (int i = 0; i < BATCH; i++) tot += part[i];
        out[0] = tot;
    }
}

extern "C" void kernel_launch(void* const* d_in, const int* in_sizes, int n_in,
                              void* d_out, int out_size) {
    const float* emb  = (const float*)d_in[0];
    const float* pred = (const float*)d_in[1];
    const int*   lab  = (const int*)d_in[2];
    const int*   nb   = (const int*)d_in[3];

    cudaFuncSetAttribute(main_kernel, cudaFuncAttributeMaxDynamicSharedMemorySize, SMEM_BYTES);

    zero_kernel<<<9, 256>>>();
    main_kernel<<<dim3(GX, BATCH), 256, SMEM_BYTES>>>(emb, pred, lab);
    finalize_kernel<<<1, BATCH * 32>>>(nb, (float*)d_out);
}

// round 2
// speedup vs baseline: 1.5357x; 1.5357x over previous
#include <cuda_runtime.h>

#define BATCH 16
#define ECH 32
#define NCLS 3
#define HW 262144           // 512*512
#define HW2 131072
#define TILE_PX 512
#define NTILES 512          // HW / TILE_PX
#define GX 9                // persistent: grid (9,16) = 144 blocks ~= 1 wave at 1 CTA/SM
#define ROWS 514            // smem row stride (conflict-free STS.64 / LDS.64 patterns)

// shared memory layout (floats) — double-buffered
#define VALS0 0
#define VALS1 (ECH*ROWS)                 // 16448
#define META0 (2*ECH*ROWS)               // 32896
#define META1 (META0 + TILE_PX)          // 33408
#define OFF_RED (META1 + TILE_PX)        // 33920
#define OFF_SCR (OFF_RED + 8*4*32)       // 34944
#define SM_FLOATS (OFF_SCR + 32)         // 34976
#define SMEM_BYTES (SM_FLOATS*4)         // 139904

// per-block partial results (unique slots -> no zeroing, no atomics)
__device__ float g_part[BATCH][GX][4][ECH]; // [0]=sum_emb_l1 [1]=sum_hat_l1 [2]=sum_emb_l2 [3]=sum_hat_l2
__device__ float g_misc[BATCH][GX][3];      // ce, c1, c2

__global__ __launch_bounds__(256, 1)
void main_kernel(const float* __restrict__ emb,
                 const float* __restrict__ pred,
                 const int*  __restrict__ lab) {
    extern __shared__ float sm[];

    const int b    = blockIdx.y;
    const int tid  = threadIdx.x;
    const int wid  = tid >> 5;
    const int lane = tid & 31;

    const float2* emb2 = (const float2*)emb + (size_t)b * ECH  * HW2;
    const float2* pr2  = (const float2*)pred + (size_t)b * NCLS * HW2;
    const int2*   lb2  = (const int2*)lab + (size_t)b * HW2;

    // accumulators (lane == channel in phase B)
    float a1 = 0.f, h1 = 0.f, a2 = 0.f, h2 = 0.f;
    float ce = 0.f;
    int   c1 = 0, c2 = 0;

    // prefetch registers
    float2 v[ECH];
    int2   lp;
    float2 q0, q1, q2;

    // ---------------- prologue: load tile bx, consume into buf0 ----------------
    {
        const int qp = blockIdx.x * (TILE_PX / 2) + tid;
        #pragma unroll
        for (int e = 0; e < ECH; e++) v[e] = emb2[e * HW2 + qp];
        lp = lb2[qp];
        q0 = pr2[qp]; q1 = pr2[HW2 + qp]; q2 = pr2[2 * HW2 + qp];

        float* vals  = sm + VALS0;
        float* metaT = sm + META0;
        float sx = 0.f, sy = 0.f;
        #pragma unroll
        for (int e = 0; e < ECH; e++) {
            float2 w = v[e];
            sx = fmaf(w.x, w.x, sx);
            sy = fmaf(w.y, w.y, sy);
            *(float2*)&vals[e * ROWS + 2 * tid] = w;
        }
        float rx = 1.f / fmaxf(sqrtf(sx), 1e-8f);
        float ry = 1.f / fmaxf(sqrtf(sy), 1e-8f);
        metaT[2 * tid]     = (lp.x == 1) ? rx : ((lp.x == 2) ? -rx : 0.f);
        metaT[2 * tid + 1] = (lp.y == 1) ? ry : ((lp.y == 2) ? -ry : 0.f);
        c1 += (lp.x == 1) + (lp.y == 1);
        c2 += (lp.x == 2) + (lp.y == 2);
        float m   = fmaxf(q0.x, fmaxf(q1.x, q2.x));
        ce += m + __logf(__expf(q0.x - m) + __expf(q1.x - m) + __expf(q2.x - m))
              - ((lp.x == 0) ? q0.x : ((lp.x == 1) ? q1.x : q2.x));
        m = fmaxf(q0.y, fmaxf(q1.y, q2.y));
        ce += m + __logf(__expf(q0.y - m) + __expf(q1.y - m) + __expf(q2.y - m))
              - ((lp.y == 0) ? q0.y : ((lp.y == 1) ? q1.y : q2.y));
    }
    __syncthreads();

    // ---------------- pipelined main loop: 1 barrier per tile ----------------
    for (int i = 0; ; i++) {
        const int tn = blockIdx.x + (i + 1) * GX;
        const bool more = (tn < NTILES);

        // issue next tile's global loads (in flight during phase B below)
        if (more) {
            const int qp = tn * (TILE_PX / 2) + tid;
            #pragma unroll
            for (int e = 0; e < ECH; e++) v[e] = emb2[e * HW2 + qp];
            lp = lb2[qp];
            q0 = pr2[qp]; q1 = pr2[HW2 + qp]; q2 = pr2[2 * HW2 + qp];
        }

        // phase B on buffer i&1: warp = 32 channels, 64 px/warp
        {
            const float* vals  = sm + ((i & 1) ? VALS1 : VALS0);
            const float* metaT = sm + ((i & 1) ? META1 : META0);
            const float* vrow = vals  + lane * ROWS + wid * 64;
            const float* mrow = metaT + wid * 64;
            #pragma unroll 8
            for (int k = 0; k < 32; k++) {
                float2 w = *(const float2*)(vrow + 2 * k);
                float2 t = *(const float2*)(mrow + 2 * k);   // broadcast within warp
                float vh0 = w.x * fabsf(t.x);
                float vh1 = w.y * fabsf(t.y);
                if      (t.x > 0.f) { a1 += w.x; h1 += vh0; }
                else if (t.x < 0.f) { a2 += w.x; h2 += vh0; }
                if      (t.y > 0.f) { a1 += w.y; h1 += vh1; }
                else if (t.y < 0.f) { a2 += w.y; h2 += vh1; }
            }
        }
        if (!more) break;

        // consume prefetched regs into the other buffer
        {
            float* vals  = sm + (((i + 1) & 1) ? VALS1 : VALS0);
            float* metaT = sm + (((i + 1) & 1) ? META1 : META0);
            float sx = 0.f, sy = 0.f;
            #pragma unroll
            for (int e = 0; e < ECH; e++) {
                float2 w = v[e];
                sx = fmaf(w.x, w.x, sx);
                sy = fmaf(w.y, w.y, sy);
                *(float2*)&vals[e * ROWS + 2 * tid] = w;
            }
            float rx = 1.f / fmaxf(sqrtf(sx), 1e-8f);
            float ry = 1.f / fmaxf(sqrtf(sy), 1e-8f);
            metaT[2 * tid]     = (lp.x == 1) ? rx : ((lp.x == 2) ? -rx : 0.f);
            metaT[2 * tid + 1] = (lp.y == 1) ? ry : ((lp.y == 2) ? -ry : 0.f);
            c1 += (lp.x == 1) + (lp.y == 1);
            c2 += (lp.x == 2) + (lp.y == 2);
            float m   = fmaxf(q0.x, fmaxf(q1.x, q2.x));
            ce += m + __logf(__expf(q0.x - m) + __expf(q1.x - m) + __expf(q2.x - m))
                  - ((lp.x == 0) ? q0.x : ((lp.x == 1) ? q1.x : q2.x));
            m = fmaxf(q0.y, fmaxf(q1.y, q2.y));
            ce += m + __logf(__expf(q0.y - m) + __expf(q1.y - m) + __expf(q2.y - m))
                  - ((lp.y == 0) ? q0.y : ((lp.y == 1) ? q1.y : q2.y));
        }
        __syncthreads();
    }

    // ---------------- block reduction -> unique global slots ----------------
    float* red = sm + OFF_RED;
    float* scr = sm + OFF_SCR;
    __syncthreads();   // protect red/scr region reuse vs last phase B reads
    red[(wid * 4 + 0) * 32 + lane] = a1;
    red[(wid * 4 + 1) * 32 + lane] = h1;
    red[(wid * 4 + 2) * 32 + lane] = a2;
    red[(wid * 4 + 3) * 32 + lane] = h2;
    float cef = ce; float c1f = (float)c1, c2f = (float)c2;
    #pragma unroll
    for (int o = 16; o; o >>= 1) {
        cef += __shfl_xor_sync(0xffffffffu, cef, o);
        c1f += __shfl_xor_sync(0xffffffffu, c1f, o);
        c2f += __shfl_xor_sync(0xffffffffu, c2f, o);
    }
    if (lane == 0) { scr[wid] = cef; scr[8 + wid] = c1f; scr[16 + wid] = c2f; }
    __syncthreads();

    if (wid < 4) {
        float s = 0.f;
        #pragma unroll
        for (int w = 0; w < 8; w++) s += red[(w * 4 + wid) * 32 + lane];
        g_part[b][blockIdx.x][wid][lane] = s;
    }
    if (tid == 0) {
        float tce = 0.f, t1 = 0.f, t2 = 0.f;
        for (int w = 0; w < 8; w++) { tce += scr[w]; t1 += scr[8 + w]; t2 += scr[16 + w]; }
        g_misc[b][blockIdx.x][0] = tce;
        g_misc[b][blockIdx.x][1] = t1;
        g_misc[b][blockIdx.x][2] = t2;
    }
}

__global__ void finalize_kernel(const int* __restrict__ nb, float* __restrict__ out) {
    __shared__ float part[BATCH];
    const int b    = threadIdx.x >> 5;   // one warp per image
    const int lane = threadIdx.x & 31;   // lane = channel

    float s1 = 0.f, hh1 = 0.f, s2 = 0.f, hh2 = 0.f;
    float ceb = 0.f, c1 = 0.f, c2 = 0.f;
    #pragma unroll
    for (int x = 0; x < GX; x++) {
        s1  += g_part[b][x][0][lane];
        hh1 += g_part[b][x][1][lane];
        s2  += g_part[b][x][2][lane];
        hh2 += g_part[b][x][3][lane];
        ceb += g_misc[b][x][0];          // broadcast loads (same addr per warp)
        c1  += g_misc[b][x][1];
        c2  += g_misc[b][x][2];
    }
    float m1 = s1 / c1, m2 = s2 / c2;

    float A  = m1 * m1;     // ||mean1||^2
    float Bv = m2 * m2;     // ||mean2||^2
    float C  = m1 * m2;     // mean1 . mean2
    float D1 = m1 * hh1;    // mean1 . hat_sum1
    float D2 = m2 * hh2;    // mean2 . hat_sum2
    #pragma unroll
    for (int o = 16; o; o >>= 1) {
        A  += __shfl_xor_sync(0xffffffffu, A,  o);
        Bv += __shfl_xor_sync(0xffffffffu, Bv, o);
        C  += __shfl_xor_sync(0xffffffffu, C,  o);
        D1 += __shfl_xor_sync(0xffffffffu, D1, o);
        D2 += __shfl_xor_sync(0xffffffffu, D2, o);
    }

    if (lane == 0) {
        float n1 = fmaxf(sqrtf(A),  1e-12f);
        float n2 = fmaxf(sqrtf(Bv), 1e-12f);
        float intra = ((1.f - D1 / (n1 * c1)) + (1.f - D2 / (n2 * c2))) / (float)(NCLS - 1);
        float S11 = A  / (n1 * n1);
        float S22 = Bv / (n2 * n2);
        float S12 = C  / (n1 * n2);
        bool mk[NCLS][NCLS] = {};
        for (int r = 1; r < NCLS; r++) {
            for (int j = 0; j < 3; j++) {
                int n = nb[(b * NCLS + r) * 3 + j];
                if (n == 0) break;      // cumprod break semantics
                mk[r][n] = true;        // scatter-max: duplicates count once
            }
        }
        float ssum = 0.f, msum = 0.f;
        for (int r = 1; r < NCLS; r++)
            for (int c = 0; c < NCLS; c++)
                if (mk[r][c]) {
                    msum += 1.f;
                    float Sv = 0.f;
                    if (r == 1) Sv = (c == 1) ? S11 : ((c == 2) ? S12 : 0.f);
                    else        Sv = (c == 1) ? S12 : ((c == 2) ? S22 : 0.f);
                    ssum += Sv;
                }
        part[b] = intra + ssum / msum + ceb * (1.0f / (float)HW);
    }
    __syncthreads();
    if (threadIdx.x == 0) {
        float tot = 0.f;
        #pragma unroll
        for (int i = 0; i < BATCH; i++) tot += part[i];
        out[0] = tot;
    }
}

extern "C" void kernel_launch(void* const* d_in, const int* in_sizes, int n_in,
                              void* d_out, int out_size) {
    const float* emb  = (const float*)d_in[0];
    const float* pred = (const float*)d_in[1];
    const int*   lab  = (const int*)d_in[2];
    const int*   nb   = (const int*)d_in[3];

    cudaFuncSetAttribute(main_kernel, cudaFuncAttributeMaxDynamicSharedMemorySize, SMEM_BYTES);

    main_kernel<<<dim3(GX, BATCH), 256, SMEM_BYTES>>>(emb, pred, lab);
    finalize_kernel<<<1, BATCH * 32>>>(nb, (float*)d_out);
}